// round 1
// baseline (speedup 1.0000x reference)
#include <cuda_runtime.h>
#include <math.h>

#define MTOK 50176
#define CCH 384
#define HWN 3136
#define PI_F 3.14159265358979323846f

// ---------------- scratch (static device allocations; no cudaMalloc) ----------------
__device__ float g_xt[(size_t)MTOK * CCH];
__device__ float g_xg[(size_t)MTOK * CCH];
__device__ float g_z [(size_t)MTOK * CCH];
__device__ float g_t1[(size_t)MTOK * CCH];
__device__ float g_u0[(size_t)MTOK * CCH];
__device__ float g_v0[(size_t)MTOK * CCH];
__device__ float g_cosb[(size_t)HWN * CCH];
__device__ float g_sinb[(size_t)HWN * CCH];
__device__ float g_D[56 * 56];

// ---------------- DCT matrix init (orthonormal DCT-II) ----------------
__global__ void dct_init_k(float* D) {
    int idx = blockIdx.x * 256 + threadIdx.x;
    if (idx < 56 * 56) {
        int k = idx / 56, n = idx % 56;
        double v = cos(3.14159265358979323846 * (2.0 * n + 1.0) * k / 112.0) * sqrt(2.0 / 56.0);
        if (k == 0) v *= (1.0 / sqrt(2.0));
        D[idx] = (float)v;
    }
}

// ---------------- depthwise 3x3 conv (SAME) + write token-major [B,HW,C] ----------------
__global__ void dwconv_k(const float* __restrict__ x, const float* __restrict__ w,
                         const float* __restrict__ bias, float* __restrict__ xt) {
    __shared__ float s[8][33];
    int tx = threadIdx.x;          // 0..31 over w
    int ty = threadIdx.y;          // 0..7 over c
    int wseg = blockIdx.x & 1;
    int h = blockIdx.x >> 1;
    int c = blockIdx.y * 8 + ty;
    int b = blockIdx.z;
    int ww = wseg * 32 + tx;

    if (ww < 56) {
        float acc = bias[c];
        const float* xp = x + ((size_t)(b * CCH + c) * 56) * 56;
        const float* wp = w + c * 9;
        #pragma unroll
        for (int kh = 0; kh < 3; kh++) {
            int hh = h + kh - 1;
            if (hh < 0 || hh >= 56) continue;
            #pragma unroll
            for (int kw = 0; kw < 3; kw++) {
                int wc = ww + kw - 1;
                if (wc < 0 || wc >= 56) continue;
                acc += xp[hh * 56 + wc] * wp[kh * 3 + kw];
            }
        }
        s[ty][tx] = acc;
    }
    __syncthreads();
    // transposed write: 8 consecutive channels per token chunk
    int tid = ty * 32 + tx;
    int wi = tid >> 3;     // 0..31  (w within tile)
    int ci = tid & 7;      // 0..7   (c within tile)
    int wo = wseg * 32 + wi;
    if (wo < 56) {
        int cout = blockIdx.y * 8 + ci;
        size_t tok = (size_t)b * HWN + h * 56 + wo;
        xt[tok * CCH + cout] = s[ci][wi];
    }
}

// ---------------- generic SGEMM: O[m,n] = sum_k A[m,k]*W[n,k] (+epilogues) ----------------
// EPI 0: +bias, split: n<384 -> O0, else O1 (stride 384 each)
// EPI 1: (+bias if non-null) -> O0[m*N+n]
// EPI 2: relu(+bias) -> t ; O0 = cos(c*t), O1 = sin(c*t)/(c+1e-6)
#define BM 128
#define BN 64
#define BK 16

template <int EPI>
__global__ void __launch_bounds__(256) gemm_k(
    const float* __restrict__ A, const float* __restrict__ Wt,
    const float* __restrict__ bias, const float* __restrict__ cptr,
    float* __restrict__ O0, float* __restrict__ O1,
    int M, int N, int K) {
    __shared__ float As[BK][BM + 4];
    __shared__ float Ws[BK][BN + 4];
    int tid = threadIdx.x;
    int m0 = blockIdx.y * BM;
    int n0 = blockIdx.x * BN;
    int mt = tid >> 4;   // 0..15
    int nt = tid & 15;   // 0..15

    float acc[8][4];
    #pragma unroll
    for (int i = 0; i < 8; i++)
        #pragma unroll
        for (int j = 0; j < 4; j++) acc[i][j] = 0.f;

    for (int k0 = 0; k0 < K; k0 += BK) {
        #pragma unroll
        for (int u = 0; u < 2; u++) {
            int f = tid + u * 256;
            int r = f >> 2, cq = f & 3;
            float4 v = make_float4(0.f, 0.f, 0.f, 0.f);
            if (m0 + r < M)
                v = *(const float4*)(A + (size_t)(m0 + r) * K + k0 + cq * 4);
            As[cq * 4 + 0][r] = v.x; As[cq * 4 + 1][r] = v.y;
            As[cq * 4 + 2][r] = v.z; As[cq * 4 + 3][r] = v.w;
        }
        {
            int r = tid >> 2, cq = tid & 3;
            float4 v = *(const float4*)(Wt + (size_t)(n0 + r) * K + k0 + cq * 4);
            Ws[cq * 4 + 0][r] = v.x; Ws[cq * 4 + 1][r] = v.y;
            Ws[cq * 4 + 2][r] = v.z; Ws[cq * 4 + 3][r] = v.w;
        }
        __syncthreads();
        #pragma unroll
        for (int kk = 0; kk < BK; kk++) {
            float4 a0 = *(const float4*)&As[kk][mt * 8];
            float4 a1 = *(const float4*)&As[kk][mt * 8 + 4];
            float4 bv = *(const float4*)&Ws[kk][nt * 4];
            float av[8] = {a0.x, a0.y, a0.z, a0.w, a1.x, a1.y, a1.z, a1.w};
            float bvv[4] = {bv.x, bv.y, bv.z, bv.w};
            #pragma unroll
            for (int i = 0; i < 8; i++)
                #pragma unroll
                for (int j = 0; j < 4; j++) acc[i][j] += av[i] * bvv[j];
        }
        __syncthreads();
    }

    float cc = 0.f, ic = 0.f;
    if (EPI == 2) { cc = cptr[0]; ic = 1.f / (cc + 1e-6f); }

    #pragma unroll
    for (int i = 0; i < 8; i++) {
        int m = m0 + mt * 8 + i;
        if (m >= M) continue;
        #pragma unroll
        for (int j = 0; j < 4; j++) {
            int n = n0 + nt * 4 + j;
            float v = acc[i][j];
            if (EPI == 0) {
                v += bias[n];
                if (n < 384) O0[(size_t)m * 384 + n] = v;
                else         O1[(size_t)m * 384 + (n - 384)] = v;
            } else if (EPI == 1) {
                if (bias) v += bias[n];
                O0[(size_t)m * N + n] = v;
            } else if (EPI == 2) {
                v += bias[n];
                v = fmaxf(v, 0.f);
                float a = cc * v;
                O0[(size_t)m * N + n] = cosf(a);
                O1[(size_t)m * N + n] = sinf(a) * ic;
            }
        }
    }
}

// ---------------- batched DCT stage: O[g][i,n] = sum_h Deff[i,h] X[g][h,n] ----------------
// Deff = D (transD=0) or D^T (transD=1). X, O contiguous [G][56][N]. gridDim = (N/128, G).
__global__ void __launch_bounds__(256) dct_k(const float* __restrict__ Dm, int transD,
                                             const float* __restrict__ X,
                                             float* __restrict__ O, int N) {
    __shared__ float Ds[56][57];
    __shared__ float Xs[56][128];
    int tid = threadIdx.x;
    int g = blockIdx.y;
    int n0 = blockIdx.x * 128;

    for (int f = tid; f < 56 * 56; f += 256) {
        int i = f / 56, k = f % 56;
        Ds[i][k] = transD ? Dm[k * 56 + i] : Dm[i * 56 + k];
    }
    const float* Xg = X + (size_t)g * 56 * N + n0;
    for (int f = tid; f < 56 * 128; f += 256) {
        int h = f >> 7, n = f & 127;
        Xs[h][n] = Xg[(size_t)h * N + n];
    }
    __syncthreads();

    int ty = tid >> 5, tx = tid & 31;
    float acc[7][4];
    #pragma unroll
    for (int ii = 0; ii < 7; ii++)
        #pragma unroll
        for (int j = 0; j < 4; j++) acc[ii][j] = 0.f;

    for (int k = 0; k < 56; k++) {
        float4 bv = *(const float4*)&Xs[k][tx * 4];
        #pragma unroll
        for (int ii = 0; ii < 7; ii++) {
            float a = Ds[ty * 7 + ii][k];
            acc[ii][0] += a * bv.x; acc[ii][1] += a * bv.y;
            acc[ii][2] += a * bv.z; acc[ii][3] += a * bv.w;
        }
    }
    float* Og = O + (size_t)g * 56 * N + n0;
    #pragma unroll
    for (int ii = 0; ii < 7; ii++) {
        int i = ty * 7 + ii;
        *(float4*)&Og[(size_t)i * N + tx * 4] =
            make_float4(acc[ii][0], acc[ii][1], acc[ii][2], acc[ii][3]);
    }
}

// ---------------- frequency-domain modulation ----------------
__global__ void mod_k(const float* __restrict__ u0, const float* __restrict__ v0,
                      const float* __restrict__ cosb, const float* __restrict__ sinb,
                      const float* __restrict__ velb, const float* __restrict__ alphap,
                      float* __restrict__ fin) {
    size_t idx = (size_t)blockIdx.x * 256 + threadIdx.x;
    if (idx >= (size_t)MTOK * CCH) return;
    int c = (int)(idx % CCH);
    size_t m = idx / CCH;
    int ij = (int)(m % HWN);
    int i = ij / 56, j = ij % 56;
    float wn = PI_F * i / 56.f, wm = PI_F * j / 56.f;
    float decay = expf(-(wn * wn + wm * wm));
    float u = u0[idx] * decay;
    float v = v0[idx];
    if (ij == 0) v += 56.f * velb[c];   // DC correction for vel bias (DCT of constant)
    v *= decay;
    float al = alphap[0];
    size_t fi = (size_t)ij * CCH + c;
    fin[idx] = cosb[fi] * u + sinb[fi] * (v + 0.5f * al * u);
}

// ---------------- LayerNorm over C + SiLU gate ----------------
__global__ void ln_gate_k(const float* __restrict__ y, const float* __restrict__ z,
                          const float* __restrict__ g, const float* __restrict__ b,
                          float* __restrict__ out) {
    int warp = threadIdx.x >> 5, lane = threadIdx.x & 31;
    size_t m = (size_t)blockIdx.x * 8 + warp;
    const float* yr = y + m * CCH;
    float vals[12];
    float s = 0.f;
    #pragma unroll
    for (int t = 0; t < 12; t++) { vals[t] = yr[lane + t * 32]; s += vals[t]; }
    #pragma unroll
    for (int o = 16; o > 0; o >>= 1) s += __shfl_xor_sync(0xffffffff, s, o);
    float mu = s * (1.f / 384.f);
    float q = 0.f;
    #pragma unroll
    for (int t = 0; t < 12; t++) { float d = vals[t] - mu; q += d * d; }
    #pragma unroll
    for (int o = 16; o > 0; o >>= 1) q += __shfl_xor_sync(0xffffffff, q, o);
    float rstd = rsqrtf(q * (1.f / 384.f) + 1e-5f);
    #pragma unroll
    for (int t = 0; t < 12; t++) {
        int c = lane + t * 32;
        float yn = (vals[t] - mu) * rstd * g[c] + b[c];
        float zz = z[m * CCH + c];
        out[m * CCH + c] = yn * (zz / (1.f + expf(-zz)));
    }
}

// ---------------- [B,HW,C] -> [B,C,HW] transpose ----------------
__global__ void transpose_k(const float* __restrict__ in, float* __restrict__ out) {
    __shared__ float s[32][33];
    int tx = threadIdx.x, ty = threadIdx.y;
    int hw0 = blockIdx.x * 32;
    int c0 = blockIdx.y * 32;
    int b = blockIdx.z;
    #pragma unroll
    for (int r = 0; r < 4; r++) {
        int hw = hw0 + ty + r * 8;
        s[ty + r * 8][tx] = in[((size_t)b * HWN + hw) * CCH + c0 + tx];
    }
    __syncthreads();
    #pragma unroll
    for (int r = 0; r < 4; r++) {
        int c = c0 + ty + r * 8;
        out[((size_t)b * CCH + c) * HWN + hw0 + tx] = s[tx][ty + r * 8];
    }
}

// ---------------- launch ----------------
extern "C" void kernel_launch(void* const* d_in, const int* in_sizes, int n_in,
                              void* d_out, int out_size) {
    const float* x          = (const float*)d_in[0];
    const float* freq_embed = (const float*)d_in[1];
    const float* dw_w       = (const float*)d_in[2];
    const float* dw_b       = (const float*)d_in[3];
    const float* lin_w      = (const float*)d_in[4];
    const float* lin_b      = (const float*)d_in[5];
    const float* vel_w      = (const float*)d_in[6];
    const float* vel_b      = (const float*)d_in[7];
    const float* tok_w      = (const float*)d_in[8];
    const float* tok_b      = (const float*)d_in[9];
    const float* ln_g       = (const float*)d_in[10];
    const float* ln_b       = (const float*)d_in[11];
    const float* out_w      = (const float*)d_in[12];
    const float* out_b      = (const float*)d_in[13];
    const float* cptr       = (const float*)d_in[14];
    const float* alphap     = (const float*)d_in[15];
    float* outp = (float*)d_out;

    float *xt, *xg, *z, *t1, *u0, *v0, *cb, *sb, *Dm;
    cudaGetSymbolAddress((void**)&xt, g_xt);
    cudaGetSymbolAddress((void**)&xg, g_xg);
    cudaGetSymbolAddress((void**)&z,  g_z);
    cudaGetSymbolAddress((void**)&t1, g_t1);
    cudaGetSymbolAddress((void**)&u0, g_u0);
    cudaGetSymbolAddress((void**)&v0, g_v0);
    cudaGetSymbolAddress((void**)&cb, g_cosb);
    cudaGetSymbolAddress((void**)&sb, g_sinb);
    cudaGetSymbolAddress((void**)&Dm, g_D);

    dct_init_k<<<13, 256>>>(Dm);

    // depthwise conv -> token-major xt
    dwconv_k<<<dim3(112, 48, 16), dim3(32, 8)>>>(x, dw_w, dw_b, xt);

    // xz = xt @ lin_w.T + lin_b ; split -> xg, z
    gemm_k<0><<<dim3(768 / BN, MTOK / BM), 256>>>(xt, lin_w, lin_b, nullptr, xg, z,
                                                  MTOK, 768, 384);

    // u0 = DCT2(xg)   (two separable stages, token-major)
    dct_k<<<dim3(168, 16), 256>>>(Dm, 0, xg, t1, 21504);
    dct_k<<<dim3(3, 896), 256>>>(Dm, 0, t1, u0, 384);

    // v0 = u0 @ vel_w.T   (DCT and channel-mixing commute; bias handled at DC)
    gemm_k<1><<<dim3(384 / BN, MTOK / BM), 256>>>(u0, vel_w, nullptr, nullptr, v0, nullptr,
                                                  MTOK, 384, 384);

    // cos/sin modulation tables from freq_embed
    gemm_k<2><<<dim3(384 / BN, (HWN + BM - 1) / BM), 256>>>(freq_embed, tok_w, tok_b, cptr,
                                                            cb, sb, HWN, 384, 384);

    // final = cos*u0d + sin*(v0d + 0.5*alpha*u0d)  (with decay) -> t1
    mod_k<<<(unsigned)(((size_t)MTOK * CCH + 255) / 256), 256>>>(u0, v0, cb, sb, vel_b,
                                                                 alphap, t1);

    // y = IDCT2(final) -> u0
    dct_k<<<dim3(168, 16), 256>>>(Dm, 1, t1, xg, 21504);
    dct_k<<<dim3(3, 896), 256>>>(Dm, 1, xg, u0, 384);

    // LayerNorm + SiLU(z) gate -> v0
    ln_gate_k<<<MTOK / 8, 256>>>(u0, z, ln_g, ln_b, v0);

    // out = gated @ out_w.T + out_b -> t1 (token-major), then transpose to NCHW
    gemm_k<1><<<dim3(384 / BN, MTOK / BM), 256>>>(v0, out_w, out_b, nullptr, t1, nullptr,
                                                  MTOK, 384, 384);
    transpose_k<<<dim3(98, 12, 16), dim3(32, 8)>>>(t1, outp);
}

// round 2
// speedup vs baseline: 1.5148x; 1.5148x over previous
#include <cuda_runtime.h>
#include <math.h>

#define MTOK 50176
#define CCH 384
#define HWN 3136
#define PI_F 3.14159265358979323846f

// ---------------- scratch ----------------
__device__ float g_xt[(size_t)MTOK * CCH];
__device__ float g_xg[(size_t)MTOK * CCH];
__device__ float g_z [(size_t)MTOK * CCH];
__device__ float g_t1[(size_t)MTOK * CCH];
__device__ float g_u0[(size_t)MTOK * CCH];
__device__ float g_v0[(size_t)MTOK * CCH];
__device__ float g_cosb[(size_t)HWN * CCH];
__device__ float g_sinb[(size_t)HWN * CCH];
__device__ float g_D[56 * 56];

// ---------------- DCT matrix init ----------------
__global__ void dct_init_k(float* D) {
    int idx = blockIdx.x * 256 + threadIdx.x;
    if (idx < 56 * 56) {
        int k = idx / 56, n = idx % 56;
        double v = cos(3.14159265358979323846 * (2.0 * n + 1.0) * k / 112.0) * sqrt(2.0 / 56.0);
        if (k == 0) v *= (1.0 / sqrt(2.0));
        D[idx] = (float)v;
    }
}

// ---------------- depthwise 3x3 conv -> token-major ----------------
__global__ void dwconv_k(const float* __restrict__ x, const float* __restrict__ w,
                         const float* __restrict__ bias, float* __restrict__ xt) {
    __shared__ float s[8][33];
    int tx = threadIdx.x, ty = threadIdx.y;
    int wseg = blockIdx.x & 1;
    int h = blockIdx.x >> 1;
    int c = blockIdx.y * 8 + ty;
    int b = blockIdx.z;
    int ww = wseg * 32 + tx;

    if (ww < 56) {
        float acc = bias[c];
        const float* xp = x + ((size_t)(b * CCH + c) * 56) * 56;
        const float* wp = w + c * 9;
        #pragma unroll
        for (int kh = 0; kh < 3; kh++) {
            int hh = h + kh - 1;
            if (hh < 0 || hh >= 56) continue;
            #pragma unroll
            for (int kw = 0; kw < 3; kw++) {
                int wc = ww + kw - 1;
                if (wc < 0 || wc >= 56) continue;
                acc += xp[hh * 56 + wc] * wp[kh * 3 + kw];
            }
        }
        s[ty][tx] = acc;
    }
    __syncthreads();
    int tid = ty * 32 + tx;
    int wi = tid >> 3, ci = tid & 7;
    int wo = wseg * 32 + wi;
    if (wo < 56) {
        int cout = blockIdx.y * 8 + ci;
        size_t tok = (size_t)b * HWN + h * 56 + wo;
        xt[tok * CCH + cout] = s[ci][wi];
    }
}

// ---------------- TF32 tensor-core GEMM: O[m,n] = sum_k A[m,k]*W[n,k] ----------------
// Requires M % 128 == 0, N % 128 == 0, K % 16 == 0.
// EPI 0: +bias, split at n=384 -> O0 / O1 (each stride 384)
// EPI 1: (+bias if non-null) -> O0[m*N+n]
#define TBM 128
#define TBN 128
#define TBK 16
#define SPAD 136

__device__ __forceinline__ unsigned f2tf32(float x) {
    unsigned r;
    asm("cvt.rna.tf32.f32 %0, %1;" : "=r"(r) : "f"(x));
    return r;
}

template <int EPI>
__global__ void __launch_bounds__(256) gemm_tc(
    const float* __restrict__ A, const float* __restrict__ Wt,
    const float* __restrict__ bias,
    float* __restrict__ O0, float* __restrict__ O1,
    int M, int N, int K) {
    __shared__ unsigned As[TBK][SPAD];
    __shared__ unsigned Bs[TBK][SPAD];

    int tid = threadIdx.x;
    int lane = tid & 31;
    int warp = tid >> 5;
    int wm = warp & 1;        // 2 warps over M (64 each)
    int wn = warp >> 1;       // 4 warps over N (32 each)
    int m0 = blockIdx.y * TBM;
    int n0 = blockIdx.x * TBN;
    int grp = lane >> 2;      // 0..7
    int qd = lane & 3;        // 0..3

    float acc[4][4][4];
    #pragma unroll
    for (int i = 0; i < 4; i++)
        #pragma unroll
        for (int j = 0; j < 4; j++)
            #pragma unroll
            for (int r = 0; r < 4; r++) acc[i][j][r] = 0.f;

    for (int k0 = 0; k0 < K; k0 += TBK) {
        #pragma unroll
        for (int u = 0; u < 2; u++) {
            int f = tid + u * 256;
            int r = f >> 2, q = f & 3;
            float4 v = *(const float4*)(A + (size_t)(m0 + r) * K + k0 + q * 4);
            As[q * 4 + 0][r] = f2tf32(v.x);
            As[q * 4 + 1][r] = f2tf32(v.y);
            As[q * 4 + 2][r] = f2tf32(v.z);
            As[q * 4 + 3][r] = f2tf32(v.w);
        }
        #pragma unroll
        for (int u = 0; u < 2; u++) {
            int f = tid + u * 256;
            int r = f >> 2, q = f & 3;
            float4 v = *(const float4*)(Wt + (size_t)(n0 + r) * K + k0 + q * 4);
            Bs[q * 4 + 0][r] = f2tf32(v.x);
            Bs[q * 4 + 1][r] = f2tf32(v.y);
            Bs[q * 4 + 2][r] = f2tf32(v.z);
            Bs[q * 4 + 3][r] = f2tf32(v.w);
        }
        __syncthreads();

        #pragma unroll
        for (int kk = 0; kk < TBK; kk += 8) {
            unsigned af[4][4], bf[4][2];
            #pragma unroll
            for (int mt = 0; mt < 4; mt++) {
                int mb = wm * 64 + mt * 16;
                af[mt][0] = As[kk + qd][mb + grp];
                af[mt][1] = As[kk + qd][mb + grp + 8];
                af[mt][2] = As[kk + qd + 4][mb + grp];
                af[mt][3] = As[kk + qd + 4][mb + grp + 8];
            }
            #pragma unroll
            for (int nt = 0; nt < 4; nt++) {
                int nb = wn * 32 + nt * 8;
                bf[nt][0] = Bs[kk + qd][nb + grp];
                bf[nt][1] = Bs[kk + qd + 4][nb + grp];
            }
            #pragma unroll
            for (int mt = 0; mt < 4; mt++)
                #pragma unroll
                for (int nt = 0; nt < 4; nt++) {
                    asm volatile(
                        "mma.sync.aligned.m16n8k8.row.col.f32.tf32.tf32.f32 "
                        "{%0,%1,%2,%3}, {%4,%5,%6,%7}, {%8,%9}, {%0,%1,%2,%3};"
                        : "+f"(acc[mt][nt][0]), "+f"(acc[mt][nt][1]),
                          "+f"(acc[mt][nt][2]), "+f"(acc[mt][nt][3])
                        : "r"(af[mt][0]), "r"(af[mt][1]), "r"(af[mt][2]), "r"(af[mt][3]),
                          "r"(bf[nt][0]), "r"(bf[nt][1]));
                }
        }
        __syncthreads();
    }

    #pragma unroll
    for (int mt = 0; mt < 4; mt++) {
        int row0 = m0 + wm * 64 + mt * 16 + grp;
        #pragma unroll
        for (int nt = 0; nt < 4; nt++) {
            int col = n0 + wn * 32 + nt * 8 + qd * 2;
            float b0 = 0.f, b1 = 0.f;
            if (EPI == 0 || bias) { b0 = bias[col]; b1 = bias[col + 1]; }
            #pragma unroll
            for (int half = 0; half < 2; half++) {
                int row = row0 + half * 8;
                float v0 = acc[mt][nt][half * 2 + 0] + b0;
                float v1 = acc[mt][nt][half * 2 + 1] + b1;
                if (EPI == 0) {
                    if (col < 384)
                        *(float2*)&O0[(size_t)row * 384 + col] = make_float2(v0, v1);
                    else
                        *(float2*)&O1[(size_t)row * 384 + (col - 384)] = make_float2(v0, v1);
                } else {
                    *(float2*)&O0[(size_t)row * N + col] = make_float2(v0, v1);
                }
            }
        }
    }
}

// ---------------- fp32 FFMA GEMM (kept for cos/sin table: precision-sensitive) ----------------
#define BM 128
#define BN 64
#define BK 16

__global__ void __launch_bounds__(256) gemm_cs(
    const float* __restrict__ A, const float* __restrict__ Wt,
    const float* __restrict__ bias, const float* __restrict__ cptr,
    float* __restrict__ O0, float* __restrict__ O1,
    int M, int N, int K) {
    __shared__ float As[BK][BM + 4];
    __shared__ float Ws[BK][BN + 4];
    int tid = threadIdx.x;
    int m0 = blockIdx.y * BM;
    int n0 = blockIdx.x * BN;
    int mt = tid >> 4;
    int nt = tid & 15;

    float acc[8][4];
    #pragma unroll
    for (int i = 0; i < 8; i++)
        #pragma unroll
        for (int j = 0; j < 4; j++) acc[i][j] = 0.f;

    for (int k0 = 0; k0 < K; k0 += BK) {
        #pragma unroll
        for (int u = 0; u < 2; u++) {
            int f = tid + u * 256;
            int r = f >> 2, cq = f & 3;
            float4 v = make_float4(0.f, 0.f, 0.f, 0.f);
            if (m0 + r < M)
                v = *(const float4*)(A + (size_t)(m0 + r) * K + k0 + cq * 4);
            As[cq * 4 + 0][r] = v.x; As[cq * 4 + 1][r] = v.y;
            As[cq * 4 + 2][r] = v.z; As[cq * 4 + 3][r] = v.w;
        }
        {
            int r = tid >> 2, cq = tid & 3;
            float4 v = *(const float4*)(Wt + (size_t)(n0 + r) * K + k0 + cq * 4);
            Ws[cq * 4 + 0][r] = v.x; Ws[cq * 4 + 1][r] = v.y;
            Ws[cq * 4 + 2][r] = v.z; Ws[cq * 4 + 3][r] = v.w;
        }
        __syncthreads();
        #pragma unroll
        for (int kk = 0; kk < BK; kk++) {
            float4 a0 = *(const float4*)&As[kk][mt * 8];
            float4 a1 = *(const float4*)&As[kk][mt * 8 + 4];
            float4 bv = *(const float4*)&Ws[kk][nt * 4];
            float av[8] = {a0.x, a0.y, a0.z, a0.w, a1.x, a1.y, a1.z, a1.w};
            float bvv[4] = {bv.x, bv.y, bv.z, bv.w};
            #pragma unroll
            for (int i = 0; i < 8; i++)
                #pragma unroll
                for (int j = 0; j < 4; j++) acc[i][j] += av[i] * bvv[j];
        }
        __syncthreads();
    }

    float cc = cptr[0], ic = 1.f / (cc + 1e-6f);

    #pragma unroll
    for (int i = 0; i < 8; i++) {
        int m = m0 + mt * 8 + i;
        if (m >= M) continue;
        #pragma unroll
        for (int j = 0; j < 4; j++) {
            int n = n0 + nt * 4 + j;
            float v = acc[i][j] + bias[n];
            v = fmaxf(v, 0.f);
            float a = cc * v;
            O0[(size_t)m * N + n] = cosf(a);
            O1[(size_t)m * N + n] = sinf(a) * ic;
        }
    }
}

// ---------------- batched DCT stage ----------------
__global__ void __launch_bounds__(256) dct_k(const float* __restrict__ Dm, int transD,
                                             const float* __restrict__ X,
                                             float* __restrict__ O, int N) {
    __shared__ float Ds[56][57];
    __shared__ float Xs[56][128];
    int tid = threadIdx.x;
    int g = blockIdx.y;
    int n0 = blockIdx.x * 128;

    for (int f = tid; f < 56 * 56; f += 256) {
        int i = f / 56, k = f % 56;
        Ds[i][k] = transD ? Dm[k * 56 + i] : Dm[i * 56 + k];
    }
    const float* Xg = X + (size_t)g * 56 * N + n0;
    for (int f = tid; f < 56 * 128; f += 256) {
        int h = f >> 7, n = f & 127;
        Xs[h][n] = Xg[(size_t)h * N + n];
    }
    __syncthreads();

    int ty = tid >> 5, tx = tid & 31;
    float acc[7][4];
    #pragma unroll
    for (int ii = 0; ii < 7; ii++)
        #pragma unroll
        for (int j = 0; j < 4; j++) acc[ii][j] = 0.f;

    for (int k = 0; k < 56; k++) {
        float4 bv = *(const float4*)&Xs[k][tx * 4];
        #pragma unroll
        for (int ii = 0; ii < 7; ii++) {
            float a = Ds[ty * 7 + ii][k];
            acc[ii][0] += a * bv.x; acc[ii][1] += a * bv.y;
            acc[ii][2] += a * bv.z; acc[ii][3] += a * bv.w;
        }
    }
    float* Og = O + (size_t)g * 56 * N + n0;
    #pragma unroll
    for (int ii = 0; ii < 7; ii++) {
        int i = ty * 7 + ii;
        *(float4*)&Og[(size_t)i * N + tx * 4] =
            make_float4(acc[ii][0], acc[ii][1], acc[ii][2], acc[ii][3]);
    }
}

// ---------------- frequency-domain modulation ----------------
__global__ void mod_k(const float* __restrict__ u0, const float* __restrict__ v0,
                      const float* __restrict__ cosb, const float* __restrict__ sinb,
                      const float* __restrict__ velb, const float* __restrict__ alphap,
                      float* __restrict__ fin) {
    size_t idx = (size_t)blockIdx.x * 256 + threadIdx.x;
    if (idx >= (size_t)MTOK * CCH) return;
    int c = (int)(idx % CCH);
    size_t m = idx / CCH;
    int ij = (int)(m % HWN);
    int i = ij / 56, j = ij % 56;
    float wn = PI_F * i / 56.f, wm = PI_F * j / 56.f;
    float decay = expf(-(wn * wn + wm * wm));
    float u = u0[idx] * decay;
    float v = v0[idx];
    if (ij == 0) v += 56.f * velb[c];
    v *= decay;
    float al = alphap[0];
    size_t fi = (size_t)ij * CCH + c;
    fin[idx] = cosb[fi] * u + sinb[fi] * (v + 0.5f * al * u);
}

// ---------------- LayerNorm + SiLU gate ----------------
__global__ void ln_gate_k(const float* __restrict__ y, const float* __restrict__ z,
                          const float* __restrict__ g, const float* __restrict__ b,
                          float* __restrict__ out) {
    int warp = threadIdx.x >> 5, lane = threadIdx.x & 31;
    size_t m = (size_t)blockIdx.x * 8 + warp;
    const float* yr = y + m * CCH;
    float vals[12];
    float s = 0.f;
    #pragma unroll
    for (int t = 0; t < 12; t++) { vals[t] = yr[lane + t * 32]; s += vals[t]; }
    #pragma unroll
    for (int o = 16; o > 0; o >>= 1) s += __shfl_xor_sync(0xffffffff, s, o);
    float mu = s * (1.f / 384.f);
    float q = 0.f;
    #pragma unroll
    for (int t = 0; t < 12; t++) { float d = vals[t] - mu; q += d * d; }
    #pragma unroll
    for (int o = 16; o > 0; o >>= 1) q += __shfl_xor_sync(0xffffffff, q, o);
    float rstd = rsqrtf(q * (1.f / 384.f) + 1e-5f);
    #pragma unroll
    for (int t = 0; t < 12; t++) {
        int c = lane + t * 32;
        float yn = (vals[t] - mu) * rstd * g[c] + b[c];
        float zz = z[m * CCH + c];
        out[m * CCH + c] = yn * (zz / (1.f + expf(-zz)));
    }
}

// ---------------- [B,HW,C] -> [B,C,HW] transpose ----------------
__global__ void transpose_k(const float* __restrict__ in, float* __restrict__ out) {
    __shared__ float s[32][33];
    int tx = threadIdx.x, ty = threadIdx.y;
    int hw0 = blockIdx.x * 32;
    int c0 = blockIdx.y * 32;
    int b = blockIdx.z;
    #pragma unroll
    for (int r = 0; r < 4; r++) {
        int hw = hw0 + ty + r * 8;
        s[ty + r * 8][tx] = in[((size_t)b * HWN + hw) * CCH + c0 + tx];
    }
    __syncthreads();
    #pragma unroll
    for (int r = 0; r < 4; r++) {
        int c = c0 + ty + r * 8;
        out[((size_t)b * CCH + c) * HWN + hw0 + tx] = s[tx][ty + r * 8];
    }
}

// ---------------- launch ----------------
extern "C" void kernel_launch(void* const* d_in, const int* in_sizes, int n_in,
                              void* d_out, int out_size) {
    const float* x          = (const float*)d_in[0];
    const float* freq_embed = (const float*)d_in[1];
    const float* dw_w       = (const float*)d_in[2];
    const float* dw_b       = (const float*)d_in[3];
    const float* lin_w      = (const float*)d_in[4];
    const float* lin_b      = (const float*)d_in[5];
    const float* vel_w      = (const float*)d_in[6];
    const float* vel_b      = (const float*)d_in[7];
    const float* tok_w      = (const float*)d_in[8];
    const float* tok_b      = (const float*)d_in[9];
    const float* ln_g       = (const float*)d_in[10];
    const float* ln_b       = (const float*)d_in[11];
    const float* out_w      = (const float*)d_in[12];
    const float* out_b      = (const float*)d_in[13];
    const float* cptr       = (const float*)d_in[14];
    const float* alphap     = (const float*)d_in[15];
    float* outp = (float*)d_out;

    float *xt, *xg, *z, *t1, *u0, *v0, *cb, *sb, *Dm;
    cudaGetSymbolAddress((void**)&xt, g_xt);
    cudaGetSymbolAddress((void**)&xg, g_xg);
    cudaGetSymbolAddress((void**)&z,  g_z);
    cudaGetSymbolAddress((void**)&t1, g_t1);
    cudaGetSymbolAddress((void**)&u0, g_u0);
    cudaGetSymbolAddress((void**)&v0, g_v0);
    cudaGetSymbolAddress((void**)&cb, g_cosb);
    cudaGetSymbolAddress((void**)&sb, g_sinb);
    cudaGetSymbolAddress((void**)&Dm, g_D);

    dct_init_k<<<13, 256>>>(Dm);

    // depthwise conv -> token-major xt
    dwconv_k<<<dim3(112, 48, 16), dim3(32, 8)>>>(x, dw_w, dw_b, xt);

    // xz = xt @ lin_w.T + lin_b ; split -> xg, z   (TF32 TC)
    gemm_tc<0><<<dim3(768 / TBN, MTOK / TBM), 256>>>(xt, lin_w, lin_b, xg, z,
                                                     MTOK, 768, 384);

    // u0 = DCT2(xg)
    dct_k<<<dim3(168, 16), 256>>>(Dm, 0, xg, t1, 21504);
    dct_k<<<dim3(3, 896), 256>>>(Dm, 0, t1, u0, 384);

    // v0 = u0 @ vel_w.T  (TF32 TC; bias handled at DC in mod_k)
    gemm_tc<1><<<dim3(384 / TBN, MTOK / TBM), 256>>>(u0, vel_w, nullptr, v0, nullptr,
                                                     MTOK, 384, 384);

    // cos/sin modulation tables (fp32 FFMA: precision-sensitive, tiny)
    gemm_cs<<<dim3(384 / BN, (HWN + BM - 1) / BM), 256>>>(freq_embed, tok_w, tok_b, cptr,
                                                          cb, sb, HWN, 384, 384);

    // final = cos*u0d + sin*(v0d + 0.5*alpha*u0d) -> t1
    mod_k<<<(unsigned)(((size_t)MTOK * CCH + 255) / 256), 256>>>(u0, v0, cb, sb, vel_b,
                                                                 alphap, t1);

    // y = IDCT2(final) -> u0
    dct_k<<<dim3(168, 16), 256>>>(Dm, 1, t1, xg, 21504);
    dct_k<<<dim3(3, 896), 256>>>(Dm, 1, xg, u0, 384);

    // LayerNorm + SiLU(z) gate -> v0
    ln_gate_k<<<MTOK / 8, 256>>>(u0, z, ln_g, ln_b, v0);

    // out = gated @ out_w.T + out_b (TF32 TC) -> t1, then transpose to NCHW
    gemm_tc<1><<<dim3(384 / TBN, MTOK / TBM), 256>>>(v0, out_w, out_b, t1, nullptr,
                                                     MTOK, 384, 384);
    transpose_k<<<dim3(98, 12, 16), dim3(32, 8)>>>(t1, outp);
}

// round 3
// speedup vs baseline: 1.6225x; 1.0711x over previous
#include <cuda_runtime.h>
#include <math.h>

#define MTOK 50176
#define CCH 384
#define HWN 3136
#define PI_F 3.14159265358979323846f

// ---------------- scratch ----------------
__device__ float g_xt[(size_t)MTOK * CCH];
__device__ float g_xg[(size_t)MTOK * CCH];
__device__ float g_z [(size_t)MTOK * CCH];
__device__ float g_t1[(size_t)MTOK * CCH];
__device__ float g_u0[(size_t)MTOK * CCH];
__device__ float g_v0[(size_t)MTOK * CCH];
__device__ float g_cosb[(size_t)HWN * CCH];
__device__ float g_sinb[(size_t)HWN * CCH];
__device__ float g_D[56 * 56];

// ---------------- DCT matrix init ----------------
__global__ void dct_init_k(float* D) {
    int idx = blockIdx.x * 256 + threadIdx.x;
    if (idx < 56 * 56) {
        int k = idx / 56, n = idx % 56;
        double v = cos(3.14159265358979323846 * (2.0 * n + 1.0) * k / 112.0) * sqrt(2.0 / 56.0);
        if (k == 0) v *= (1.0 / sqrt(2.0));
        D[idx] = (float)v;
    }
}

// ---------------- depthwise 3x3 conv -> token-major ----------------
__global__ void dwconv_k(const float* __restrict__ x, const float* __restrict__ w,
                         const float* __restrict__ bias, float* __restrict__ xt) {
    __shared__ float s[8][33];
    int tx = threadIdx.x, ty = threadIdx.y;
    int wseg = blockIdx.x & 1;
    int h = blockIdx.x >> 1;
    int c = blockIdx.y * 8 + ty;
    int b = blockIdx.z;
    int ww = wseg * 32 + tx;

    if (ww < 56) {
        float acc = bias[c];
        const float* xp = x + ((size_t)(b * CCH + c) * 56) * 56;
        const float* wp = w + c * 9;
        #pragma unroll
        for (int kh = 0; kh < 3; kh++) {
            int hh = h + kh - 1;
            if (hh < 0 || hh >= 56) continue;
            #pragma unroll
            for (int kw = 0; kw < 3; kw++) {
                int wc = ww + kw - 1;
                if (wc < 0 || wc >= 56) continue;
                acc += xp[hh * 56 + wc] * wp[kh * 3 + kw];
            }
        }
        s[ty][tx] = acc;
    }
    __syncthreads();
    int tid = ty * 32 + tx;
    int wi = tid >> 3, ci = tid & 7;
    int wo = wseg * 32 + wi;
    if (wo < 56) {
        int cout = blockIdx.y * 8 + ci;
        size_t tok = (size_t)b * HWN + h * 56 + wo;
        xt[tok * CCH + cout] = s[ci][wi];
    }
}

// ---------------- TF32 tensor-core GEMM, double-buffered ----------------
// O[m,n] = sum_k A[m,k]*W[n,k]. M%128==0, N%128==0, K%16==0.
// EPI 0: +bias, split at n=384 -> O0 / O1 (each stride 384)
// EPI 1: (+bias if non-null) -> O0[m*N+n]
// EPI 2: wave modulation fused (vel GEMM): O0 = fin, uses U/cosb/sinb/velb/alphap
#define TBM 128
#define TBN 128
#define TBK 16
#define SPAD 136

__device__ __forceinline__ unsigned f2tf32(float x) {
    unsigned r;
    asm("cvt.rna.tf32.f32 %0, %1;" : "=r"(r) : "f"(x));
    return r;
}

template <int EPI>
__global__ void __launch_bounds__(256) gemm_tc(
    const float* __restrict__ A, const float* __restrict__ Wt,
    const float* __restrict__ bias,
    float* __restrict__ O0, float* __restrict__ O1,
    const float* __restrict__ U, const float* __restrict__ cosb,
    const float* __restrict__ sinb, const float* __restrict__ velb,
    const float* __restrict__ alphap,
    int M, int N, int K) {
    __shared__ unsigned As[2][TBK][SPAD];
    __shared__ unsigned Bs[2][TBK][SPAD];

    int tid = threadIdx.x;
    int lane = tid & 31;
    int warp = tid >> 5;
    int wm = warp & 1;
    int wn = warp >> 1;
    int m0 = blockIdx.y * TBM;
    int n0 = blockIdx.x * TBN;
    int grp = lane >> 2;
    int qd = lane & 3;
    int lr = tid >> 2;      // 0..63 (row base for loads)
    int lq = tid & 3;       // 0..3  (k quad)

    float acc[4][4][4];
    #pragma unroll
    for (int i = 0; i < 4; i++)
        #pragma unroll
        for (int j = 0; j < 4; j++)
            #pragma unroll
            for (int r = 0; r < 4; r++) acc[i][j][r] = 0.f;

    const float* Abase = A + (size_t)(m0 + lr) * K + lq * 4;
    const float* Bbase = Wt + (size_t)(n0 + lr) * K + lq * 4;
    size_t rowstrA = (size_t)64 * K;

    float4 pa[2], pb[2];
    #pragma unroll
    for (int u = 0; u < 2; u++) {
        pa[u] = *(const float4*)(Abase + u * rowstrA);
        pb[u] = *(const float4*)(Bbase + u * rowstrA);
    }

    int stages = K / TBK;
    // store stage 0
    #pragma unroll
    for (int u = 0; u < 2; u++) {
        int r = lr + u * 64;
        As[0][lq * 4 + 0][r] = f2tf32(pa[u].x);
        As[0][lq * 4 + 1][r] = f2tf32(pa[u].y);
        As[0][lq * 4 + 2][r] = f2tf32(pa[u].z);
        As[0][lq * 4 + 3][r] = f2tf32(pa[u].w);
        Bs[0][lq * 4 + 0][r] = f2tf32(pb[u].x);
        Bs[0][lq * 4 + 1][r] = f2tf32(pb[u].y);
        Bs[0][lq * 4 + 2][r] = f2tf32(pb[u].z);
        Bs[0][lq * 4 + 3][r] = f2tf32(pb[u].w);
    }
    __syncthreads();

    for (int it = 0; it < stages; it++) {
        int s = it & 1;
        bool more = (it + 1 < stages);
        if (more) {
            int k0 = (it + 1) * TBK;
            #pragma unroll
            for (int u = 0; u < 2; u++) {
                pa[u] = *(const float4*)(Abase + k0 + u * rowstrA);
                pb[u] = *(const float4*)(Bbase + k0 + u * rowstrA);
            }
        }
        #pragma unroll
        for (int kk = 0; kk < TBK; kk += 8) {
            unsigned af[4][4], bf[4][2];
            #pragma unroll
            for (int mt = 0; mt < 4; mt++) {
                int mb = wm * 64 + mt * 16;
                af[mt][0] = As[s][kk + qd][mb + grp];
                af[mt][1] = As[s][kk + qd][mb + grp + 8];
                af[mt][2] = As[s][kk + qd + 4][mb + grp];
                af[mt][3] = As[s][kk + qd + 4][mb + grp + 8];
            }
            #pragma unroll
            for (int nt = 0; nt < 4; nt++) {
                int nb = wn * 32 + nt * 8;
                bf[nt][0] = Bs[s][kk + qd][nb + grp];
                bf[nt][1] = Bs[s][kk + qd + 4][nb + grp];
            }
            #pragma unroll
            for (int mt = 0; mt < 4; mt++)
                #pragma unroll
                for (int nt = 0; nt < 4; nt++) {
                    asm volatile(
                        "mma.sync.aligned.m16n8k8.row.col.f32.tf32.tf32.f32 "
                        "{%0,%1,%2,%3}, {%4,%5,%6,%7}, {%8,%9}, {%0,%1,%2,%3};"
                        : "+f"(acc[mt][nt][0]), "+f"(acc[mt][nt][1]),
                          "+f"(acc[mt][nt][2]), "+f"(acc[mt][nt][3])
                        : "r"(af[mt][0]), "r"(af[mt][1]), "r"(af[mt][2]), "r"(af[mt][3]),
                          "r"(bf[nt][0]), "r"(bf[nt][1]));
                }
        }
        if (more) {
            int d = s ^ 1;
            #pragma unroll
            for (int u = 0; u < 2; u++) {
                int r = lr + u * 64;
                As[d][lq * 4 + 0][r] = f2tf32(pa[u].x);
                As[d][lq * 4 + 1][r] = f2tf32(pa[u].y);
                As[d][lq * 4 + 2][r] = f2tf32(pa[u].z);
                As[d][lq * 4 + 3][r] = f2tf32(pa[u].w);
                Bs[d][lq * 4 + 0][r] = f2tf32(pb[u].x);
                Bs[d][lq * 4 + 1][r] = f2tf32(pb[u].y);
                Bs[d][lq * 4 + 2][r] = f2tf32(pb[u].z);
                Bs[d][lq * 4 + 3][r] = f2tf32(pb[u].w);
            }
        }
        __syncthreads();
    }

    float al = 0.f;
    if (EPI == 2) al = alphap[0];

    #pragma unroll
    for (int mt = 0; mt < 4; mt++) {
        int row0 = m0 + wm * 64 + mt * 16 + grp;
        #pragma unroll
        for (int nt = 0; nt < 4; nt++) {
            int col = n0 + wn * 32 + nt * 8 + qd * 2;
            float b0 = 0.f, b1 = 0.f;
            if (EPI == 0 || (EPI == 1 && bias)) { b0 = bias[col]; b1 = bias[col + 1]; }
            #pragma unroll
            for (int half = 0; half < 2; half++) {
                int row = row0 + half * 8;
                float v0 = acc[mt][nt][half * 2 + 0] + b0;
                float v1 = acc[mt][nt][half * 2 + 1] + b1;
                if (EPI == 0) {
                    if (col < 384)
                        *(float2*)&O0[(size_t)row * 384 + col] = make_float2(v0, v1);
                    else
                        *(float2*)&O1[(size_t)row * 384 + (col - 384)] = make_float2(v0, v1);
                } else if (EPI == 1) {
                    *(float2*)&O0[(size_t)row * N + col] = make_float2(v0, v1);
                } else {
                    // wave modulation epilogue (N == 384)
                    int ij = row % HWN;
                    int i = ij / 56, j = ij % 56;
                    float wnv = PI_F * i / 56.f, wmv = PI_F * j / 56.f;
                    float decay = expf(-(wnv * wnv + wmv * wmv));
                    float2 uv = *(const float2*)&U[(size_t)row * 384 + col];
                    float ua = uv.x * decay, ub = uv.y * decay;
                    float va = v0, vb = v1;
                    if (ij == 0) { va += 56.f * velb[col]; vb += 56.f * velb[col + 1]; }
                    va *= decay; vb *= decay;
                    float2 cv = *(const float2*)&cosb[(size_t)ij * 384 + col];
                    float2 sv = *(const float2*)&sinb[(size_t)ij * 384 + col];
                    float fa = cv.x * ua + sv.x * (va + 0.5f * al * ua);
                    float fb = cv.y * ub + sv.y * (vb + 0.5f * al * ub);
                    *(float2*)&O0[(size_t)row * 384 + col] = make_float2(fa, fb);
                }
            }
        }
    }
}

// ---------------- fp32 FFMA GEMM for cos/sin table ----------------
#define BM 128
#define BN 64
#define BK 16

__global__ void __launch_bounds__(256) gemm_cs(
    const float* __restrict__ A, const float* __restrict__ Wt,
    const float* __restrict__ bias, const float* __restrict__ cptr,
    float* __restrict__ O0, float* __restrict__ O1,
    int M, int N, int K) {
    __shared__ float As[BK][BM + 4];
    __shared__ float Ws[BK][BN + 4];
    int tid = threadIdx.x;
    int m0 = blockIdx.y * BM;
    int n0 = blockIdx.x * BN;
    int mt = tid >> 4;
    int nt = tid & 15;

    float acc[8][4];
    #pragma unroll
    for (int i = 0; i < 8; i++)
        #pragma unroll
        for (int j = 0; j < 4; j++) acc[i][j] = 0.f;

    for (int k0 = 0; k0 < K; k0 += BK) {
        #pragma unroll
        for (int u = 0; u < 2; u++) {
            int f = tid + u * 256;
            int r = f >> 2, cq = f & 3;
            float4 v = make_float4(0.f, 0.f, 0.f, 0.f);
            if (m0 + r < M)
                v = *(const float4*)(A + (size_t)(m0 + r) * K + k0 + cq * 4);
            As[cq * 4 + 0][r] = v.x; As[cq * 4 + 1][r] = v.y;
            As[cq * 4 + 2][r] = v.z; As[cq * 4 + 3][r] = v.w;
        }
        {
            int r = tid >> 2, cq = tid & 3;
            float4 v = *(const float4*)(Wt + (size_t)(n0 + r) * K + k0 + cq * 4);
            Ws[cq * 4 + 0][r] = v.x; Ws[cq * 4 + 1][r] = v.y;
            Ws[cq * 4 + 2][r] = v.z; Ws[cq * 4 + 3][r] = v.w;
        }
        __syncthreads();
        #pragma unroll
        for (int kk = 0; kk < BK; kk++) {
            float4 a0 = *(const float4*)&As[kk][mt * 8];
            float4 a1 = *(const float4*)&As[kk][mt * 8 + 4];
            float4 bv = *(const float4*)&Ws[kk][nt * 4];
            float av[8] = {a0.x, a0.y, a0.z, a0.w, a1.x, a1.y, a1.z, a1.w};
            float bvv[4] = {bv.x, bv.y, bv.z, bv.w};
            #pragma unroll
            for (int i = 0; i < 8; i++)
                #pragma unroll
                for (int j = 0; j < 4; j++) acc[i][j] += av[i] * bvv[j];
        }
        __syncthreads();
    }

    float cc = cptr[0], ic = 1.f / (cc + 1e-6f);

    #pragma unroll
    for (int i = 0; i < 8; i++) {
        int m = m0 + mt * 8 + i;
        if (m >= M) continue;
        #pragma unroll
        for (int j = 0; j < 4; j++) {
            int n = n0 + nt * 4 + j;
            float v = acc[i][j] + bias[n];
            v = fmaxf(v, 0.f);
            float a = cc * v;
            O0[(size_t)m * N + n] = cosf(a);
            O1[(size_t)m * N + n] = sinf(a) * ic;
        }
    }
}

// ---------------- batched DCT stage, 2 groups per block ----------------
// O[g][i,n] = sum_h Deff[i,h] X[g][h,n]; Deff = D or D^T. N-tile 128.
// grid = (N/128, G/2). Dynamic smem: Ds[56][57] + Xs[2][56][128].
__global__ void __launch_bounds__(256) dct2_k(const float* __restrict__ Dm, int transD,
                                              const float* __restrict__ X,
                                              float* __restrict__ O, int N) {
    extern __shared__ float sm[];
    float* Ds = sm;                       // 56*57
    float* Xs = sm + 56 * 57;             // 2*56*128
    int tid = threadIdx.x;
    int g0 = blockIdx.y * 2;
    int n0 = blockIdx.x * 128;

    for (int f = tid; f < 56 * 56; f += 256) {
        int i = f / 56, k = f % 56;
        Ds[i * 57 + k] = transD ? Dm[k * 56 + i] : Dm[i * 56 + k];
    }
    #pragma unroll
    for (int gg = 0; gg < 2; gg++) {
        const float* Xg = X + (size_t)(g0 + gg) * 56 * N + n0;
        float* Xd = Xs + gg * 56 * 128;
        for (int f = tid; f < 56 * 128; f += 256) {
            int h = f >> 7, n = f & 127;
            Xd[h * 128 + n] = Xg[(size_t)h * N + n];
        }
    }
    __syncthreads();

    int ty = tid >> 5, tx = tid & 31;
    float acc[2][7][4];
    #pragma unroll
    for (int gg = 0; gg < 2; gg++)
        #pragma unroll
        for (int ii = 0; ii < 7; ii++)
            #pragma unroll
            for (int j = 0; j < 4; j++) acc[gg][ii][j] = 0.f;

    for (int k = 0; k < 56; k++) {
        float4 b0 = *(const float4*)&Xs[k * 128 + tx * 4];
        float4 b1 = *(const float4*)&Xs[56 * 128 + k * 128 + tx * 4];
        #pragma unroll
        for (int ii = 0; ii < 7; ii++) {
            float a = Ds[(ty * 7 + ii) * 57 + k];
            acc[0][ii][0] += a * b0.x; acc[0][ii][1] += a * b0.y;
            acc[0][ii][2] += a * b0.z; acc[0][ii][3] += a * b0.w;
            acc[1][ii][0] += a * b1.x; acc[1][ii][1] += a * b1.y;
            acc[1][ii][2] += a * b1.z; acc[1][ii][3] += a * b1.w;
        }
    }
    #pragma unroll
    for (int gg = 0; gg < 2; gg++) {
        float* Og = O + (size_t)(g0 + gg) * 56 * N + n0;
        #pragma unroll
        for (int ii = 0; ii < 7; ii++) {
            int i = ty * 7 + ii;
            *(float4*)&Og[(size_t)i * N + tx * 4] =
                make_float4(acc[gg][ii][0], acc[gg][ii][1], acc[gg][ii][2], acc[gg][ii][3]);
        }
    }
}

// ---------------- LayerNorm + SiLU gate ----------------
__global__ void ln_gate_k(const float* __restrict__ y, const float* __restrict__ z,
                          const float* __restrict__ g, const float* __restrict__ b,
                          float* __restrict__ out) {
    int warp = threadIdx.x >> 5, lane = threadIdx.x & 31;
    size_t m = (size_t)blockIdx.x * 8 + warp;
    const float* yr = y + m * CCH;
    float vals[12];
    float s = 0.f;
    #pragma unroll
    for (int t = 0; t < 12; t++) { vals[t] = yr[lane + t * 32]; s += vals[t]; }
    #pragma unroll
    for (int o = 16; o > 0; o >>= 1) s += __shfl_xor_sync(0xffffffff, s, o);
    float mu = s * (1.f / 384.f);
    float q = 0.f;
    #pragma unroll
    for (int t = 0; t < 12; t++) { float d = vals[t] - mu; q += d * d; }
    #pragma unroll
    for (int o = 16; o > 0; o >>= 1) q += __shfl_xor_sync(0xffffffff, q, o);
    float rstd = rsqrtf(q * (1.f / 384.f) + 1e-5f);
    #pragma unroll
    for (int t = 0; t < 12; t++) {
        int c = lane + t * 32;
        float yn = (vals[t] - mu) * rstd * g[c] + b[c];
        float zz = z[m * CCH + c];
        out[m * CCH + c] = yn * (zz / (1.f + expf(-zz)));
    }
}

// ---------------- [B,HW,C] -> [B,C,HW] transpose ----------------
__global__ void transpose_k(const float* __restrict__ in, float* __restrict__ out) {
    __shared__ float s[32][33];
    int tx = threadIdx.x, ty = threadIdx.y;
    int hw0 = blockIdx.x * 32;
    int c0 = blockIdx.y * 32;
    int b = blockIdx.z;
    #pragma unroll
    for (int r = 0; r < 4; r++) {
        int hw = hw0 + ty + r * 8;
        s[ty + r * 8][tx] = in[((size_t)b * HWN + hw) * CCH + c0 + tx];
    }
    __syncthreads();
    #pragma unroll
    for (int r = 0; r < 4; r++) {
        int c = c0 + ty + r * 8;
        out[((size_t)b * CCH + c) * HWN + hw0 + tx] = s[tx][ty + r * 8];
    }
}

// ---------------- launch ----------------
extern "C" void kernel_launch(void* const* d_in, const int* in_sizes, int n_in,
                              void* d_out, int out_size) {
    const float* x          = (const float*)d_in[0];
    const float* freq_embed = (const float*)d_in[1];
    const float* dw_w       = (const float*)d_in[2];
    const float* dw_b       = (const float*)d_in[3];
    const float* lin_w      = (const float*)d_in[4];
    const float* lin_b      = (const float*)d_in[5];
    const float* vel_w      = (const float*)d_in[6];
    const float* vel_b      = (const float*)d_in[7];
    const float* tok_w      = (const float*)d_in[8];
    const float* tok_b      = (const float*)d_in[9];
    const float* ln_g       = (const float*)d_in[10];
    const float* ln_b       = (const float*)d_in[11];
    const float* out_w      = (const float*)d_in[12];
    const float* out_b      = (const float*)d_in[13];
    const float* cptr       = (const float*)d_in[14];
    const float* alphap     = (const float*)d_in[15];
    float* outp = (float*)d_out;

    float *xt, *xg, *z, *t1, *u0, *v0, *cb, *sb, *Dm;
    cudaGetSymbolAddress((void**)&xt, g_xt);
    cudaGetSymbolAddress((void**)&xg, g_xg);
    cudaGetSymbolAddress((void**)&z,  g_z);
    cudaGetSymbolAddress((void**)&t1, g_t1);
    cudaGetSymbolAddress((void**)&u0, g_u0);
    cudaGetSymbolAddress((void**)&v0, g_v0);
    cudaGetSymbolAddress((void**)&cb, g_cosb);
    cudaGetSymbolAddress((void**)&sb, g_sinb);
    cudaGetSymbolAddress((void**)&Dm, g_D);

    const int dctSmem = (56 * 57 + 2 * 56 * 128) * 4;   // 70112 B
    cudaFuncSetAttribute(dct2_k, cudaFuncAttributeMaxDynamicSharedMemorySize, dctSmem);

    dct_init_k<<<13, 256>>>(Dm);

    // depthwise conv -> token-major xt
    dwconv_k<<<dim3(112, 48, 16), dim3(32, 8)>>>(x, dw_w, dw_b, xt);

    // cos/sin tables (independent; fp32 for precision)
    gemm_cs<<<dim3(384 / BN, (HWN + BM - 1) / BM), 256>>>(freq_embed, tok_w, tok_b, cptr,
                                                          cb, sb, HWN, 384, 384);

    // xz = xt @ lin_w.T + lin_b ; split -> xg, z
    gemm_tc<0><<<dim3(768 / TBN, MTOK / TBM), 256>>>(xt, lin_w, lin_b, xg, z,
                                                     nullptr, nullptr, nullptr, nullptr, nullptr,
                                                     MTOK, 768, 384);

    // u0 = DCT2(xg)
    dct2_k<<<dim3(168, 8), 256, dctSmem>>>(Dm, 0, xg, t1, 21504);
    dct2_k<<<dim3(3, 448), 256, dctSmem>>>(Dm, 0, t1, u0, 384);

    // fin = mod(u0, u0 @ vel_w.T) -> t1   (mod fused into epilogue)
    gemm_tc<2><<<dim3(384 / TBN, MTOK / TBM), 256>>>(u0, vel_w, nullptr, t1, nullptr,
                                                     u0, cb, sb, vel_b, alphap,
                                                     MTOK, 384, 384);

    // y = IDCT2(fin) -> u0
    dct2_k<<<dim3(168, 8), 256, dctSmem>>>(Dm, 1, t1, xg, 21504);
    dct2_k<<<dim3(3, 448), 256, dctSmem>>>(Dm, 1, xg, u0, 384);

    // LayerNorm + SiLU(z) gate -> v0
    ln_gate_k<<<MTOK / 8, 256>>>(u0, z, ln_g, ln_b, v0);

    // out = gated @ out_w.T + out_b -> t1, then transpose to NCHW
    gemm_tc<1><<<dim3(384 / TBN, MTOK / TBM), 256>>>(v0, out_w, out_b, t1, nullptr,
                                                     nullptr, nullptr, nullptr, nullptr, nullptr,
                                                     MTOK, 384, 384);
    transpose_k<<<dim3(98, 12, 16), dim3(32, 8)>>>(t1, outp);
}

// round 4
// speedup vs baseline: 1.8089x; 1.1149x over previous
#include <cuda_runtime.h>
#include <math.h>

#define MTOK 50176
#define CCH 384
#define HWN 3136
#define PI_F 3.14159265358979323846f

// ---------------- scratch ----------------
__device__ float g_xt[(size_t)MTOK * CCH];
__device__ float g_xg[(size_t)MTOK * CCH];
__device__ float g_z [(size_t)MTOK * CCH];
__device__ float g_t1[(size_t)MTOK * CCH];
__device__ float g_u0[(size_t)MTOK * CCH];
__device__ float g_v0[(size_t)MTOK * CCH];
__device__ float g_cosb[(size_t)HWN * CCH];
__device__ float g_sinb[(size_t)HWN * CCH];
__device__ float g_D[56 * 56];

// ---------------- DCT matrix init ----------------
__global__ void dct_init_k(float* D) {
    int idx = blockIdx.x * 256 + threadIdx.x;
    if (idx < 56 * 56) {
        int k = idx / 56, n = idx % 56;
        double v = cos(3.14159265358979323846 * (2.0 * n + 1.0) * k / 112.0) * sqrt(2.0 / 56.0);
        if (k == 0) v *= (1.0 / sqrt(2.0));
        D[idx] = (float)v;
    }
}

// ---------------- depthwise 3x3 conv -> token-major ----------------
__global__ void dwconv_k(const float* __restrict__ x, const float* __restrict__ w,
                         const float* __restrict__ bias, float* __restrict__ xt) {
    __shared__ float s[8][33];
    int tx = threadIdx.x, ty = threadIdx.y;
    int wseg = blockIdx.x & 1;
    int h = blockIdx.x >> 1;
    int c = blockIdx.y * 8 + ty;
    int b = blockIdx.z;
    int ww = wseg * 32 + tx;

    if (ww < 56) {
        float acc = bias[c];
        const float* xp = x + ((size_t)(b * CCH + c) * 56) * 56;
        const float* wp = w + c * 9;
        #pragma unroll
        for (int kh = 0; kh < 3; kh++) {
            int hh = h + kh - 1;
            if (hh < 0 || hh >= 56) continue;
            #pragma unroll
            for (int kw = 0; kw < 3; kw++) {
                int wc = ww + kw - 1;
                if (wc < 0 || wc >= 56) continue;
                acc += xp[hh * 56 + wc] * wp[kh * 3 + kw];
            }
        }
        s[ty][tx] = acc;
    }
    __syncthreads();
    int tid = ty * 32 + tx;
    int wi = tid >> 3, ci = tid & 7;
    int wo = wseg * 32 + wi;
    if (wo < 56) {
        int cout = blockIdx.y * 8 + ci;
        size_t tok = (size_t)b * HWN + h * 56 + wo;
        xt[tok * CCH + cout] = s[ci][wi];
    }
}

// ---------------- TF32 tensor-core GEMM, double-buffered, vectorized LDS ----------------
// Smem layout [row][16 k] (row stride 16 words: conflict-free). K-permutation:
// thread qd consumes physical k {4qd..4qd+3}; A and B agree, so sum unchanged.
// EPI 0: +bias, split at n=384 -> O0 / O1 ; EPI 1: (+bias) -> O0 ; EPI 2: wave mod.
#define TBM 128
#define TBN 128
#define TBK 16

__device__ __forceinline__ unsigned f2tf32(float x) {
    unsigned r;
    asm("cvt.rna.tf32.f32 %0, %1;" : "=r"(r) : "f"(x));
    return r;
}

template <int EPI>
__global__ void __launch_bounds__(256, 2) gemm_tc(
    const float* __restrict__ A, const float* __restrict__ Wt,
    const float* __restrict__ bias,
    float* __restrict__ O0, float* __restrict__ O1,
    const float* __restrict__ U, const float* __restrict__ cosb,
    const float* __restrict__ sinb, const float* __restrict__ velb,
    const float* __restrict__ alphap,
    int M, int N, int K) {
    __shared__ unsigned As[2][TBM][TBK];
    __shared__ unsigned Bs[2][TBN][TBK];

    int tid = threadIdx.x;
    int lane = tid & 31;
    int warp = tid >> 5;
    int wm = warp & 1;
    int wn = warp >> 1;
    int m0 = blockIdx.y * TBM;
    int n0 = blockIdx.x * TBN;
    int grp = lane >> 2;
    int qd = lane & 3;
    int lr = tid >> 2;      // 0..63 (row base for loads)
    int lq = tid & 3;       // 0..3  (k quad)

    float acc[4][4][4];
    #pragma unroll
    for (int i = 0; i < 4; i++)
        #pragma unroll
        for (int j = 0; j < 4; j++)
            #pragma unroll
            for (int r = 0; r < 4; r++) acc[i][j][r] = 0.f;

    const float* Abase = A + (size_t)(m0 + lr) * K + lq * 4;
    const float* Bbase = Wt + (size_t)(n0 + lr) * K + lq * 4;
    size_t rowstrA = (size_t)64 * K;

    float4 pa[2], pb[2];
    #pragma unroll
    for (int u = 0; u < 2; u++) {
        pa[u] = *(const float4*)(Abase + u * rowstrA);
        pb[u] = *(const float4*)(Bbase + u * rowstrA);
    }

    int stages = K / TBK;
    #pragma unroll
    for (int u = 0; u < 2; u++) {
        int r = lr + u * 64;
        As[0][r][lq * 4 + 0] = f2tf32(pa[u].x);
        As[0][r][lq * 4 + 1] = f2tf32(pa[u].y);
        As[0][r][lq * 4 + 2] = f2tf32(pa[u].z);
        As[0][r][lq * 4 + 3] = f2tf32(pa[u].w);
        Bs[0][r][lq * 4 + 0] = f2tf32(pb[u].x);
        Bs[0][r][lq * 4 + 1] = f2tf32(pb[u].y);
        Bs[0][r][lq * 4 + 2] = f2tf32(pb[u].z);
        Bs[0][r][lq * 4 + 3] = f2tf32(pb[u].w);
    }
    __syncthreads();

    for (int it = 0; it < stages; it++) {
        int s = it & 1;
        bool more = (it + 1 < stages);
        if (more) {
            int k0 = (it + 1) * TBK;
            #pragma unroll
            for (int u = 0; u < 2; u++) {
                pa[u] = *(const float4*)(Abase + k0 + u * rowstrA);
                pb[u] = *(const float4*)(Bbase + k0 + u * rowstrA);
            }
        }
        // fragment loads: one LDS.128 per row covers both 8-wide k-chunks
        uint4 alo[4], ahi[4];
        #pragma unroll
        for (int mt = 0; mt < 4; mt++) {
            int mb = wm * 64 + mt * 16;
            alo[mt] = *(const uint4*)&As[s][mb + grp][qd * 4];
            ahi[mt] = *(const uint4*)&As[s][mb + grp + 8][qd * 4];
        }
        #pragma unroll
        for (int nt = 0; nt < 4; nt++) {
            int nb = wn * 32 + nt * 8;
            uint4 bv = *(const uint4*)&Bs[s][nb + grp][qd * 4];
            #pragma unroll
            for (int mt = 0; mt < 4; mt++) {
                // chunk 0: physical k {4qd, 4qd+1}
                asm volatile(
                    "mma.sync.aligned.m16n8k8.row.col.f32.tf32.tf32.f32 "
                    "{%0,%1,%2,%3}, {%4,%5,%6,%7}, {%8,%9}, {%0,%1,%2,%3};"
                    : "+f"(acc[mt][nt][0]), "+f"(acc[mt][nt][1]),
                      "+f"(acc[mt][nt][2]), "+f"(acc[mt][nt][3])
                    : "r"(alo[mt].x), "r"(ahi[mt].x), "r"(alo[mt].y), "r"(ahi[mt].y),
                      "r"(bv.x), "r"(bv.y));
                // chunk 1: physical k {4qd+2, 4qd+3}
                asm volatile(
                    "mma.sync.aligned.m16n8k8.row.col.f32.tf32.tf32.f32 "
                    "{%0,%1,%2,%3}, {%4,%5,%6,%7}, {%8,%9}, {%0,%1,%2,%3};"
                    : "+f"(acc[mt][nt][0]), "+f"(acc[mt][nt][1]),
                      "+f"(acc[mt][nt][2]), "+f"(acc[mt][nt][3])
                    : "r"(alo[mt].z), "r"(ahi[mt].z), "r"(alo[mt].w), "r"(ahi[mt].w),
                      "r"(bv.z), "r"(bv.w));
            }
        }
        if (more) {
            int d = s ^ 1;
            #pragma unroll
            for (int u = 0; u < 2; u++) {
                int r = lr + u * 64;
                As[d][r][lq * 4 + 0] = f2tf32(pa[u].x);
                As[d][r][lq * 4 + 1] = f2tf32(pa[u].y);
                As[d][r][lq * 4 + 2] = f2tf32(pa[u].z);
                As[d][r][lq * 4 + 3] = f2tf32(pa[u].w);
                Bs[d][r][lq * 4 + 0] = f2tf32(pb[u].x);
                Bs[d][r][lq * 4 + 1] = f2tf32(pb[u].y);
                Bs[d][r][lq * 4 + 2] = f2tf32(pb[u].z);
                Bs[d][r][lq * 4 + 3] = f2tf32(pb[u].w);
            }
        }
        __syncthreads();
    }

    float al = 0.f;
    if (EPI == 2) al = alphap[0];

    #pragma unroll
    for (int mt = 0; mt < 4; mt++) {
        int row0 = m0 + wm * 64 + mt * 16 + grp;
        #pragma unroll
        for (int nt = 0; nt < 4; nt++) {
            int col = n0 + wn * 32 + nt * 8 + qd * 2;
            float b0 = 0.f, b1 = 0.f;
            if (EPI == 0 || (EPI == 1 && bias)) { b0 = bias[col]; b1 = bias[col + 1]; }
            #pragma unroll
            for (int half = 0; half < 2; half++) {
                int row = row0 + half * 8;
                float v0 = acc[mt][nt][half * 2 + 0] + b0;
                float v1 = acc[mt][nt][half * 2 + 1] + b1;
                if (EPI == 0) {
                    if (col < 384)
                        *(float2*)&O0[(size_t)row * 384 + col] = make_float2(v0, v1);
                    else
                        *(float2*)&O1[(size_t)row * 384 + (col - 384)] = make_float2(v0, v1);
                } else if (EPI == 1) {
                    *(float2*)&O0[(size_t)row * N + col] = make_float2(v0, v1);
                } else {
                    int ij = row % HWN;
                    int i = ij / 56, j = ij % 56;
                    float wnv = PI_F * i / 56.f, wmv = PI_F * j / 56.f;
                    float decay = expf(-(wnv * wnv + wmv * wmv));
                    float2 uv = *(const float2*)&U[(size_t)row * 384 + col];
                    float ua = uv.x * decay, ub = uv.y * decay;
                    float va = v0, vb = v1;
                    if (ij == 0) { va += 56.f * velb[col]; vb += 56.f * velb[col + 1]; }
                    va *= decay; vb *= decay;
                    float2 cv = *(const float2*)&cosb[(size_t)ij * 384 + col];
                    float2 sv = *(const float2*)&sinb[(size_t)ij * 384 + col];
                    float fa = cv.x * ua + sv.x * (va + 0.5f * al * ua);
                    float fb = cv.y * ub + sv.y * (vb + 0.5f * al * ub);
                    *(float2*)&O0[(size_t)row * 384 + col] = make_float2(fa, fb);
                }
            }
        }
    }
}

// ---------------- fp32 FFMA GEMM for cos/sin table ----------------
#define BM 128
#define BN 64
#define BK 16

__global__ void __launch_bounds__(256) gemm_cs(
    const float* __restrict__ A, const float* __restrict__ Wt,
    const float* __restrict__ bias, const float* __restrict__ cptr,
    float* __restrict__ O0, float* __restrict__ O1,
    int M, int N, int K) {
    __shared__ float As[BK][BM + 4];
    __shared__ float Ws[BK][BN + 4];
    int tid = threadIdx.x;
    int m0 = blockIdx.y * BM;
    int n0 = blockIdx.x * BN;
    int mt = tid >> 4;
    int nt = tid & 15;

    float acc[8][4];
    #pragma unroll
    for (int i = 0; i < 8; i++)
        #pragma unroll
        for (int j = 0; j < 4; j++) acc[i][j] = 0.f;

    for (int k0 = 0; k0 < K; k0 += BK) {
        #pragma unroll
        for (int u = 0; u < 2; u++) {
            int f = tid + u * 256;
            int r = f >> 2, cq = f & 3;
            float4 v = make_float4(0.f, 0.f, 0.f, 0.f);
            if (m0 + r < M)
                v = *(const float4*)(A + (size_t)(m0 + r) * K + k0 + cq * 4);
            As[cq * 4 + 0][r] = v.x; As[cq * 4 + 1][r] = v.y;
            As[cq * 4 + 2][r] = v.z; As[cq * 4 + 3][r] = v.w;
        }
        {
            int r = tid >> 2, cq = tid & 3;
            float4 v = *(const float4*)(Wt + (size_t)(n0 + r) * K + k0 + cq * 4);
            Ws[cq * 4 + 0][r] = v.x; Ws[cq * 4 + 1][r] = v.y;
            Ws[cq * 4 + 2][r] = v.z; Ws[cq * 4 + 3][r] = v.w;
        }
        __syncthreads();
        #pragma unroll
        for (int kk = 0; kk < BK; kk++) {
            float4 a0 = *(const float4*)&As[kk][mt * 8];
            float4 a1 = *(const float4*)&As[kk][mt * 8 + 4];
            float4 bv = *(const float4*)&Ws[kk][nt * 4];
            float av[8] = {a0.x, a0.y, a0.z, a0.w, a1.x, a1.y, a1.z, a1.w};
            float bvv[4] = {bv.x, bv.y, bv.z, bv.w};
            #pragma unroll
            for (int i = 0; i < 8; i++)
                #pragma unroll
                for (int j = 0; j < 4; j++) acc[i][j] += av[i] * bvv[j];
        }
        __syncthreads();
    }

    float cc = cptr[0], ic = 1.f / (cc + 1e-6f);

    #pragma unroll
    for (int i = 0; i < 8; i++) {
        int m = m0 + mt * 8 + i;
        if (m >= M) continue;
        #pragma unroll
        for (int j = 0; j < 4; j++) {
            int n = n0 + nt * 4 + j;
            float v = acc[i][j] + bias[n];
            v = fmaxf(v, 0.f);
            float a = cc * v;
            O0[(size_t)m * N + n] = cosf(a);
            O1[(size_t)m * N + n] = sinf(a) * ic;
        }
    }
}

// ---------------- batched DCT stage, 2 groups per block ----------------
__global__ void __launch_bounds__(256) dct2_k(const float* __restrict__ Dm, int transD,
                                              const float* __restrict__ X,
                                              float* __restrict__ O, int N) {
    extern __shared__ float sm[];
    float* Ds = sm;                       // 56*57
    float* Xs = sm + 56 * 57;             // 2*56*128
    int tid = threadIdx.x;
    int g0 = blockIdx.y * 2;
    int n0 = blockIdx.x * 128;

    for (int f = tid; f < 56 * 56; f += 256) {
        int i = f / 56, k = f % 56;
        Ds[i * 57 + k] = transD ? Dm[k * 56 + i] : Dm[i * 56 + k];
    }
    #pragma unroll
    for (int gg = 0; gg < 2; gg++) {
        const float* Xg = X + (size_t)(g0 + gg) * 56 * N + n0;
        float* Xd = Xs + gg * 56 * 128;
        for (int f = tid; f < 56 * 128; f += 256) {
            int h = f >> 7, n = f & 127;
            Xd[h * 128 + n] = Xg[(size_t)h * N + n];
        }
    }
    __syncthreads();

    int ty = tid >> 5, tx = tid & 31;
    float acc[2][7][4];
    #pragma unroll
    for (int gg = 0; gg < 2; gg++)
        #pragma unroll
        for (int ii = 0; ii < 7; ii++)
            #pragma unroll
            for (int j = 0; j < 4; j++) acc[gg][ii][j] = 0.f;

    for (int k = 0; k < 56; k++) {
        float4 b0 = *(const float4*)&Xs[k * 128 + tx * 4];
        float4 b1 = *(const float4*)&Xs[56 * 128 + k * 128 + tx * 4];
        #pragma unroll
        for (int ii = 0; ii < 7; ii++) {
            float a = Ds[(ty * 7 + ii) * 57 + k];
            acc[0][ii][0] += a * b0.x; acc[0][ii][1] += a * b0.y;
            acc[0][ii][2] += a * b0.z; acc[0][ii][3] += a * b0.w;
            acc[1][ii][0] += a * b1.x; acc[1][ii][1] += a * b1.y;
            acc[1][ii][2] += a * b1.z; acc[1][ii][3] += a * b1.w;
        }
    }
    #pragma unroll
    for (int gg = 0; gg < 2; gg++) {
        float* Og = O + (size_t)(g0 + gg) * 56 * N + n0;
        #pragma unroll
        for (int ii = 0; ii < 7; ii++) {
            int i = ty * 7 + ii;
            *(float4*)&Og[(size_t)i * N + tx * 4] =
                make_float4(acc[gg][ii][0], acc[gg][ii][1], acc[gg][ii][2], acc[gg][ii][3]);
        }
    }
}

// ---------------- LayerNorm + SiLU gate ----------------
__global__ void ln_gate_k(const float* __restrict__ y, const float* __restrict__ z,
                          const float* __restrict__ g, const float* __restrict__ b,
                          float* __restrict__ out) {
    int warp = threadIdx.x >> 5, lane = threadIdx.x & 31;
    size_t m = (size_t)blockIdx.x * 8 + warp;
    const float* yr = y + m * CCH;
    float vals[12];
    float s = 0.f;
    #pragma unroll
    for (int t = 0; t < 12; t++) { vals[t] = yr[lane + t * 32]; s += vals[t]; }
    #pragma unroll
    for (int o = 16; o > 0; o >>= 1) s += __shfl_xor_sync(0xffffffff, s, o);
    float mu = s * (1.f / 384.f);
    float q = 0.f;
    #pragma unroll
    for (int t = 0; t < 12; t++) { float d = vals[t] - mu; q += d * d; }
    #pragma unroll
    for (int o = 16; o > 0; o >>= 1) q += __shfl_xor_sync(0xffffffff, q, o);
    float rstd = rsqrtf(q * (1.f / 384.f) + 1e-5f);
    #pragma unroll
    for (int t = 0; t < 12; t++) {
        int c = lane + t * 32;
        float yn = (vals[t] - mu) * rstd * g[c] + b[c];
        float zz = z[m * CCH + c];
        out[m * CCH + c] = yn * (zz / (1.f + expf(-zz)));
    }
}

// ---------------- [B,HW,C] -> [B,C,HW] transpose ----------------
__global__ void transpose_k(const float* __restrict__ in, float* __restrict__ out) {
    __shared__ float s[32][33];
    int tx = threadIdx.x, ty = threadIdx.y;
    int hw0 = blockIdx.x * 32;
    int c0 = blockIdx.y * 32;
    int b = blockIdx.z;
    #pragma unroll
    for (int r = 0; r < 4; r++) {
        int hw = hw0 + ty + r * 8;
        s[ty + r * 8][tx] = in[((size_t)b * HWN + hw) * CCH + c0 + tx];
    }
    __syncthreads();
    #pragma unroll
    for (int r = 0; r < 4; r++) {
        int c = c0 + ty + r * 8;
        out[((size_t)b * CCH + c) * HWN + hw0 + tx] = s[tx][ty + r * 8];
    }
}

// ---------------- launch ----------------
extern "C" void kernel_launch(void* const* d_in, const int* in_sizes, int n_in,
                              void* d_out, int out_size) {
    const float* x          = (const float*)d_in[0];
    const float* freq_embed = (const float*)d_in[1];
    const float* dw_w       = (const float*)d_in[2];
    const float* dw_b       = (const float*)d_in[3];
    const float* lin_w      = (const float*)d_in[4];
    const float* lin_b      = (const float*)d_in[5];
    const float* vel_w      = (const float*)d_in[6];
    const float* vel_b      = (const float*)d_in[7];
    const float* tok_w      = (const float*)d_in[8];
    const float* tok_b      = (const float*)d_in[9];
    const float* ln_g       = (const float*)d_in[10];
    const float* ln_b       = (const float*)d_in[11];
    const float* out_w      = (const float*)d_in[12];
    const float* out_b      = (const float*)d_in[13];
    const float* cptr       = (const float*)d_in[14];
    const float* alphap     = (const float*)d_in[15];
    float* outp = (float*)d_out;

    float *xt, *xg, *z, *t1, *u0, *v0, *cb, *sb, *Dm;
    cudaGetSymbolAddress((void**)&xt, g_xt);
    cudaGetSymbolAddress((void**)&xg, g_xg);
    cudaGetSymbolAddress((void**)&z,  g_z);
    cudaGetSymbolAddress((void**)&t1, g_t1);
    cudaGetSymbolAddress((void**)&u0, g_u0);
    cudaGetSymbolAddress((void**)&v0, g_v0);
    cudaGetSymbolAddress((void**)&cb, g_cosb);
    cudaGetSymbolAddress((void**)&sb, g_sinb);
    cudaGetSymbolAddress((void**)&Dm, g_D);

    const int dctSmem = (56 * 57 + 2 * 56 * 128) * 4;   // 70112 B
    cudaFuncSetAttribute(dct2_k, cudaFuncAttributeMaxDynamicSharedMemorySize, dctSmem);

    dct_init_k<<<13, 256>>>(Dm);

    // depthwise conv -> token-major xt
    dwconv_k<<<dim3(112, 48, 16), dim3(32, 8)>>>(x, dw_w, dw_b, xt);

    // cos/sin tables (independent; fp32 for precision)
    gemm_cs<<<dim3(384 / BN, (HWN + BM - 1) / BM), 256>>>(freq_embed, tok_w, tok_b, cptr,
                                                          cb, sb, HWN, 384, 384);

    // xz = xt @ lin_w.T + lin_b ; split -> xg, z
    gemm_tc<0><<<dim3(768 / TBN, MTOK / TBM), 256>>>(xt, lin_w, lin_b, xg, z,
                                                     nullptr, nullptr, nullptr, nullptr, nullptr,
                                                     MTOK, 768, 384);

    // u0 = DCT2(xg)
    dct2_k<<<dim3(168, 8), 256, dctSmem>>>(Dm, 0, xg, t1, 21504);
    dct2_k<<<dim3(3, 448), 256, dctSmem>>>(Dm, 0, t1, u0, 384);

    // fin = mod(u0, u0 @ vel_w.T) -> t1   (mod fused into epilogue)
    gemm_tc<2><<<dim3(384 / TBN, MTOK / TBM), 256>>>(u0, vel_w, nullptr, t1, nullptr,
                                                     u0, cb, sb, vel_b, alphap,
                                                     MTOK, 384, 384);

    // y = IDCT2(fin) -> u0
    dct2_k<<<dim3(168, 8), 256, dctSmem>>>(Dm, 1, t1, xg, 21504);
    dct2_k<<<dim3(3, 448), 256, dctSmem>>>(Dm, 1, xg, u0, 384);

    // LayerNorm + SiLU(z) gate -> v0
    ln_gate_k<<<MTOK / 8, 256>>>(u0, z, ln_g, ln_b, v0);

    // out = gated @ out_w.T + out_b -> t1, then transpose to NCHW
    gemm_tc<1><<<dim3(384 / TBN, MTOK / TBM), 256>>>(v0, out_w, out_b, t1, nullptr,
                                                     nullptr, nullptr, nullptr, nullptr, nullptr,
                                                     MTOK, 384, 384);
    transpose_k<<<dim3(98, 12, 16), dim3(32, 8)>>>(t1, outp);
}